// round 3
// baseline (speedup 1.0000x reference)
#include <cuda_runtime.h>
#include <math.h>

#define BB 4
#define HH 8
#define LL 1024
#define DD 32
#define DIMM 256
#define ATT_SCALE 0.0625f   // DIM^-0.5 = 1/16

#define M1 1048576
// scratch layout (floats)
#define OFF_XQ  (0*M1)
#define OFF_XK  (1*M1)
#define OFF_XV  (2*M1)
#define OFF_RV  (3*M1)
#define OFF_Q   (4*M1)
#define OFF_K   (5*M1)
#define OFF_VM  (6*M1)
#define OFF_VRM (7*M1)
#define OFF_RCOL (8*M1)

__device__ float g_scratch[8*M1 + HH*BB*LL];

// ---------------------------------------------------------------------------
// K1: per-head projections  dst[b,h,t,d] = sum_dp src[b,t,h*32+dp] * W[dp,d]
// which: 0 -> xq (x,Wq), 1 -> xk (rx,Wk), 2 -> xv (x,Wv), 3 -> rv (rx,Wv)
// ---------------------------------------------------------------------------
__global__ __launch_bounds__(256) void proj_kernel(
    const float* __restrict__ x, const float* __restrict__ rx,
    const float* __restrict__ Wq, const float* __restrict__ Wk,
    const float* __restrict__ Wv, float* __restrict__ scratch)
{
    int tid = threadIdx.x;
    int which = blockIdx.y;
    const float* src = (which == 0 || which == 2) ? x : rx;
    const float* W = (which == 0) ? Wq : ((which == 1) ? Wk : Wv);
    float* dst = scratch + (size_t)which * M1;

    __shared__ float Ws[1024];
    __shared__ float Xs[8][32];
    for (int i = tid; i < 1024; i += 256) Ws[i] = W[i];

    int r = blockIdx.x * 8 + (tid >> 5);   // r = (b*8+h)*1024 + t
    int d = tid & 31;
    int b = r >> 13;
    int h = (r >> 10) & 7;
    int t = r & 1023;
    Xs[tid >> 5][d] = src[((size_t)(b * LL + t)) * DIMM + h * 32 + d];
    __syncthreads();

    float acc = 0.f;
    #pragma unroll
    for (int dp = 0; dp < 32; dp++) acc += Xs[tid >> 5][dp] * Ws[dp * 32 + d];
    dst[(size_t)r * 32 + d] = acc;
}

// ---------------------------------------------------------------------------
// Generic per-(b,h) SGEMM:  C[l,d] = sum_t Amat[bh][l,t] * Bm[bh][t,d]
// Amat: [32][1024][1024] row-major per bh; Bm: [32][1024][32]
// C addressing: Cb = C + b*c_b_stride + h*c_h_stride; element Cb[l*c_row+d]
// Tile: 64 rows x 32 cols, K-chunk 32, 256 threads, 8 outputs/thread.
// ---------------------------------------------------------------------------
__global__ __launch_bounds__(256) void gemm_adj(
    const float* __restrict__ Amat, const float* __restrict__ Bm,
    float* __restrict__ C, size_t c_b_stride, size_t c_h_stride, int c_row_stride)
{
    __shared__ float Ast[32][68];   // transposed A tile, padded (68*4 % 16 == 0)
    __shared__ float Bs[1024];

    int tid = threadIdx.x;
    int bh = blockIdx.y;
    const float* A  = Amat + (size_t)bh * (LL * LL);
    const float* Bb = Bm + (size_t)bh * (LL * DD);
    float* Cb = C + (size_t)(bh >> 3) * c_b_stride + (size_t)(bh & 7) * c_h_stride;
    int l0 = blockIdx.x * 64;

    int d = tid & 31, rg = tid >> 5;
    int lrow = tid >> 2, cseg = (tid & 3) * 8;

    float acc[8] = {0.f,0.f,0.f,0.f,0.f,0.f,0.f,0.f};

    for (int k0 = 0; k0 < LL; k0 += 32) {
        const float* arow = A + (size_t)(l0 + lrow) * LL + k0 + cseg;
        float4 a0 = *(const float4*)(arow);
        float4 a1 = *(const float4*)(arow + 4);
        Ast[cseg+0][lrow] = a0.x; Ast[cseg+1][lrow] = a0.y;
        Ast[cseg+2][lrow] = a0.z; Ast[cseg+3][lrow] = a0.w;
        Ast[cseg+4][lrow] = a1.x; Ast[cseg+5][lrow] = a1.y;
        Ast[cseg+6][lrow] = a1.z; Ast[cseg+7][lrow] = a1.w;
        *(float4*)&Bs[tid * 4] = *(const float4*)(Bb + (size_t)k0 * 32 + tid * 4);
        __syncthreads();

        #pragma unroll
        for (int kk = 0; kk < 32; kk++) {
            float bv = Bs[kk * 32 + d];
            float4 av0 = *(const float4*)&Ast[kk][rg * 8];
            float4 av1 = *(const float4*)&Ast[kk][rg * 8 + 4];
            acc[0] += av0.x * bv; acc[1] += av0.y * bv;
            acc[2] += av0.z * bv; acc[3] += av0.w * bv;
            acc[4] += av1.x * bv; acc[5] += av1.y * bv;
            acc[6] += av1.z * bv; acc[7] += av1.w * bv;
        }
        __syncthreads();
    }
    #pragma unroll
    for (int j = 0; j < 8; j++)
        Cb[(size_t)(l0 + rg * 8 + j) * c_row_stride + d] = acc[j];
}

// ---------------------------------------------------------------------------
// K3: attention logits + leaky + R head-mixing + adjacency mask + row softmax.
// Block = (b, 8 l-rows). Warp w computes logits for head h=w (phase A: K rows
// loaded straight from global, coalesced per lane) and then the mixed/masked
// row li=w (phase B). Two passes: stats, then normalized write.
// Deterministic (warp-shuffle reductions only). 16.5 KB static smem.
// ---------------------------------------------------------------------------
__global__ __launch_bounds__(256) void attn_kernel(
    const float* __restrict__ q, const float* __restrict__ k,
    const float* __restrict__ adj, const float* __restrict__ R,
    float* __restrict__ A_out)
{
    __shared__ float Qs[8][8][32];
    __shared__ float Ss[8][8][32];
    __shared__ float Rs[64];

    int tid = threadIdx.x, w = tid >> 5, lane = tid & 31;
    int b = blockIdx.y, l0 = blockIdx.x * 8;

    for (int i = tid; i < 2048; i += 256) {
        int h = i >> 8, li = (i >> 5) & 7, d = i & 31;
        Qs[h][li][d] = q[((size_t)((b * 8 + h) * LL + l0 + li)) * 32 + d];
    }
    if (tid < 64) Rs[tid] = R[tid];

    float rmax[8], rsum[8], rinv[8];
    #pragma unroll
    for (int i = 0; i < 8; i++) { rmax[i] = -INFINITY; rsum[i] = 0.f; rinv[i] = 0.f; }
    __syncthreads();

    const int l = l0 + w;
    const float* kb = k + ((size_t)((b * 8 + w) * LL + lane)) * 32;  // head w, row lane

    for (int pass = 0; pass < 2; pass++) {
        for (int t0 = 0; t0 < LL; t0 += 32) {
            // logits for head h = w; lane covers t = t0 + lane; 8 l rows
            {
                const float* krow = kb + (size_t)t0 * 32;
                float acc[8] = {0.f,0.f,0.f,0.f,0.f,0.f,0.f,0.f};
                #pragma unroll
                for (int d4 = 0; d4 < 32; d4 += 4) {
                    float4 kv = *(const float4*)(krow + d4);
                    #pragma unroll
                    for (int li = 0; li < 8; li++) {
                        float4 qv = *(const float4*)&Qs[w][li][d4];
                        acc[li] += qv.x*kv.x + qv.y*kv.y + qv.z*kv.z + qv.w*kv.w;
                    }
                }
                #pragma unroll
                for (int li = 0; li < 8; li++) {
                    float s = acc[li] * ATT_SCALE;
                    Ss[w][li][lane] = (s > 0.f) ? s : 0.01f * s;   // leaky_relu
                }
            }
            __syncthreads();

            // mixing + mask for row li = w
            {
                float sv[8];
                #pragma unroll
                for (int h = 0; h < 8; h++) sv[h] = Ss[h][w][lane];
                int t = t0 + lane;
                #pragma unroll
                for (int i = 0; i < 8; i++) {
                    float m = 0.f;
                    #pragma unroll
                    for (int h = 0; h < 8; h++) m += Rs[i * 8 + h] * sv[h];
                    size_t idx = ((size_t)((b * 8 + i) * LL + l)) * LL + t;
                    float a = adj[idx];
                    if (pass == 0) {
                        if (a > 0.f) {
                            float nm = fmaxf(rmax[i], m);
                            rsum[i] = rsum[i] * __expf(rmax[i] - nm) + __expf(m - nm);
                            rmax[i] = nm;
                        }
                    } else {
                        float outv = 0.f;
                        if (a > 0.f) outv = __expf(m - rmax[i]) * rinv[i];
                        A_out[idx] = outv;
                    }
                }
            }
            __syncthreads();
        }

        if (pass == 0) {
            // combine online (max,sum) across the 32 lanes of each warp
            #pragma unroll
            for (int i = 0; i < 8; i++) {
                float mx = rmax[i], sm = rsum[i];
                #pragma unroll
                for (int off = 16; off; off >>= 1) {
                    float om = __shfl_down_sync(0xffffffffu, mx, off);
                    float os = __shfl_down_sync(0xffffffffu, sm, off);
                    float nm = fmaxf(mx, om);
                    float p1 = (sm > 0.f) ? sm * __expf(mx - nm) : 0.f;
                    float p2 = (os > 0.f) ? os * __expf(om - nm) : 0.f;
                    mx = nm; sm = p1 + p2;
                }
                mx = __shfl_sync(0xffffffffu, mx, 0);
                sm = __shfl_sync(0xffffffffu, sm, 0);
                rmax[i] = mx; rsum[i] = sm;
                rinv[i] = 1.f / sm;   // diagonal always unmasked -> sm >= 1 term
            }
        }
    }
}

// ---------------------------------------------------------------------------
// K4: rcol[b,i,t] = 1 / sum_l exp(A[b,i,l,t])   (deterministic fixed order)
// ---------------------------------------------------------------------------
__global__ __launch_bounds__(256) void colsum_kernel(
    const float* __restrict__ A, float* __restrict__ rcol)
{
    int bi = blockIdx.y;
    int t = blockIdx.x * 256 + threadIdx.x;
    const float* base = A + (size_t)bi * (LL * LL);
    float s0 = 0.f, s1 = 0.f, s2 = 0.f, s3 = 0.f;
    for (int lrow = 0; lrow < LL; lrow += 4) {
        s0 += __expf(base[(size_t)(lrow + 0) * LL + t]);
        s1 += __expf(base[(size_t)(lrow + 1) * LL + t]);
        s2 += __expf(base[(size_t)(lrow + 2) * LL + t]);
        s3 += __expf(base[(size_t)(lrow + 3) * LL + t]);
    }
    rcol[bi * LL + t] = 1.f / ((s0 + s1) + (s2 + s3));
}

// ---------------------------------------------------------------------------
// K5: Ar[b,i,t,l] = exp(A[b,i,l,t]) * rcol[b,i,t]   (tiled transpose)
// ---------------------------------------------------------------------------
__global__ __launch_bounds__(256) void transpose_exp_kernel(
    const float* __restrict__ A, const float* __restrict__ rcol,
    float* __restrict__ Ar)
{
    __shared__ float Ts[32][33];
    int bi = blockIdx.z;
    int l0 = blockIdx.x * 32, t0 = blockIdx.y * 32;
    int lane = threadIdx.x & 31, wr = threadIdx.x >> 5;
    const float* base = A + (size_t)bi * (LL * LL);
    float* obase = Ar + (size_t)bi * (LL * LL);
    #pragma unroll
    for (int j = 0; j < 4; j++) {
        int lr = wr + j * 8;
        Ts[lr][lane] = base[(size_t)(l0 + lr) * LL + t0 + lane];
    }
    __syncthreads();
    #pragma unroll
    for (int j = 0; j < 4; j++) {
        int tr = wr + j * 8;
        float rc = rcol[bi * LL + t0 + tr];
        obase[(size_t)(t0 + tr) * LL + l0 + lane] = __expf(Ts[lane][tr]) * rc;
    }
}

// ---------------------------------------------------------------------------
// K6: Out[r,n] = sum_m gelu(Vm[r,m]) * Wp[m,n]   (exact gelu, erf)
// ---------------------------------------------------------------------------
__device__ __forceinline__ float gelu_exact(float v)
{
    return 0.5f * v * (1.f + erff(v * 0.70710678118654752f));
}

__global__ __launch_bounds__(256) void out_gemm(
    const float* __restrict__ Vm, const float* __restrict__ Wp,
    float* __restrict__ Out)
{
    __shared__ float Gs[32][68];
    __shared__ float Ws[1024];
    int tid = threadIdx.x;
    int r0 = blockIdx.x * 64, n0 = blockIdx.y * 32;
    int d = tid & 31, rg = tid >> 5;
    int rrow = tid >> 2, cseg = (tid & 3) * 8;

    float acc[8] = {0.f,0.f,0.f,0.f,0.f,0.f,0.f,0.f};

    for (int k0 = 0; k0 < DIMM; k0 += 32) {
        const float* vrow = Vm + (size_t)(r0 + rrow) * DIMM + k0 + cseg;
        float4 a0 = *(const float4*)(vrow);
        float4 a1 = *(const float4*)(vrow + 4);
        Gs[cseg+0][rrow] = gelu_exact(a0.x); Gs[cseg+1][rrow] = gelu_exact(a0.y);
        Gs[cseg+2][rrow] = gelu_exact(a0.z); Gs[cseg+3][rrow] = gelu_exact(a0.w);
        Gs[cseg+4][rrow] = gelu_exact(a1.x); Gs[cseg+5][rrow] = gelu_exact(a1.y);
        Gs[cseg+6][rrow] = gelu_exact(a1.z); Gs[cseg+7][rrow] = gelu_exact(a1.w);
        *(float4*)&Ws[(tid >> 3) * 32 + (tid & 7) * 4] =
            *(const float4*)(Wp + (size_t)(k0 + (tid >> 3)) * DIMM + n0 + (tid & 7) * 4);
        __syncthreads();

        #pragma unroll
        for (int kk = 0; kk < 32; kk++) {
            float bv = Ws[kk * 32 + d];
            float4 av0 = *(const float4*)&Gs[kk][rg * 8];
            float4 av1 = *(const float4*)&Gs[kk][rg * 8 + 4];
            acc[0] += av0.x * bv; acc[1] += av0.y * bv;
            acc[2] += av0.z * bv; acc[3] += av0.w * bv;
            acc[4] += av1.x * bv; acc[5] += av1.y * bv;
            acc[6] += av1.z * bv; acc[7] += av1.w * bv;
        }
        __syncthreads();
    }
    #pragma unroll
    for (int j = 0; j < 8; j++)
        Out[(size_t)(r0 + rg * 8 + j) * DIMM + n0 + d] = acc[j];
}

// ---------------------------------------------------------------------------
// Launch. Output layout (float32, concatenated in reference return order):
//   out [4,1024,256] | out_resize [4,1024,256] | A [4,8,1024,1024] | Ar [...]
// ---------------------------------------------------------------------------
extern "C" void kernel_launch(void* const* d_in, const int* in_sizes, int n_in,
                              void* d_out, int out_size)
{
    const float* x    = (const float*)d_in[0];
    const float* rx   = (const float*)d_in[1];
    const float* adj  = (const float*)d_in[2];
    const float* adjr = (const float*)d_in[3];
    const float* Wq   = (const float*)d_in[4];
    const float* Wk   = (const float*)d_in[5];
    const float* Wv   = (const float*)d_in[6];
    const float* R    = (const float*)d_in[7];
    const float* Wp   = (const float*)d_in[8];

    float* out  = (float*)d_out;
    float* outr = out + (size_t)BB * LL * DIMM;            // 1048576
    float* A    = out + (size_t)2 * BB * LL * DIMM;        // 2097152
    float* Ar   = A + (size_t)BB * HH * LL * LL;           // 35651584

    float* s = nullptr;
    cudaGetSymbolAddress((void**)&s, g_scratch);

    // K1: projections (xq, xk, xv, rv)
    proj_kernel<<<dim3(4096, 4), 256>>>(x, rx, Wq, Wk, Wv, s);

    // K2: q = adj @ xq ; k = adj_resize @ xk   -> [b,h,l,d] scratch
    gemm_adj<<<dim3(16, 32), 256>>>(adj,  s + OFF_XQ, s + OFF_Q,
                                    (size_t)HH * LL * DD, (size_t)LL * DD, DD);
    gemm_adj<<<dim3(16, 32), 256>>>(adjr, s + OFF_XK, s + OFF_K,
                                    (size_t)HH * LL * DD, (size_t)LL * DD, DD);

    // K3: logits + leaky + R-mix + mask + softmax -> A (in d_out)
    attn_kernel<<<dim3(128, 4), 256>>>(s + OFF_Q, s + OFF_K, adj, R, A);

    // K4 + K5: dual softmax on transpose -> Ar (in d_out)
    colsum_kernel<<<dim3(4, 32), 256>>>(A, s + OFF_RCOL);
    transpose_exp_kernel<<<dim3(32, 32, 32), 256>>>(A, s + OFF_RCOL, Ar);

    // v = A @ xv ; vr = Ar @ rv   -> merged [b, l, h*32+d] layout
    gemm_adj<<<dim3(16, 32), 256>>>(A,  s + OFF_XV, s + OFF_VM,
                                    (size_t)LL * DIMM, (size_t)DD, DIMM);
    gemm_adj<<<dim3(16, 32), 256>>>(Ar, s + OFF_RV, s + OFF_VRM,
                                    (size_t)LL * DIMM, (size_t)DD, DIMM);

    // K6: out = gelu(v) @ Wp ; out_resize = gelu(vr) @ Wp
    out_gemm<<<dim3(64, 8), 256>>>(s + OFF_VM,  Wp, out);
    out_gemm<<<dim3(64, 8), 256>>>(s + OFF_VRM, Wp, outr);
}

// round 4
// speedup vs baseline: 1.3192x; 1.3192x over previous
#include <cuda_runtime.h>
#include <math.h>

#define BB 4
#define HH 8
#define LL 1024
#define DD 32
#define DIMM 256
#define ATT_SCALE 0.0625f   // DIM^-0.5 = 1/16

#define M1 1048576
// scratch layout (floats)
#define OFF_XQ  (0*M1)
#define OFF_XK  (1*M1)
#define OFF_XV  (2*M1)
#define OFF_RV  (3*M1)
#define OFF_Q   (4*M1)
#define OFF_K   (5*M1)
#define OFF_VM  (6*M1)
#define OFF_VRM (7*M1)
#define OFF_RCOL (8*M1)
#define OFF_RMAX (8*M1 + 32768)
#define OFF_RINV (8*M1 + 65536)

__device__ float g_scratch[8*M1 + 3*32768];

// ---------------------------------------------------------------------------
// K1: per-head projections  dst[b,h,t,d] = sum_dp src[b,t,h*32+dp] * W[dp,d]
// which: 0 -> xq (x,Wq), 1 -> xk (rx,Wk), 2 -> xv (x,Wv), 3 -> rv (rx,Wv)
// ---------------------------------------------------------------------------
__global__ __launch_bounds__(256) void proj_kernel(
    const float* __restrict__ x, const float* __restrict__ rx,
    const float* __restrict__ Wq, const float* __restrict__ Wk,
    const float* __restrict__ Wv, float* __restrict__ scratch)
{
    int tid = threadIdx.x;
    int which = blockIdx.y;
    const float* src = (which == 0 || which == 2) ? x : rx;
    const float* W = (which == 0) ? Wq : ((which == 1) ? Wk : Wv);
    float* dst = scratch + (size_t)which * M1;

    __shared__ float Ws[1024];
    __shared__ float Xs[8][32];
    for (int i = tid; i < 1024; i += 256) Ws[i] = W[i];

    int r = blockIdx.x * 8 + (tid >> 5);   // r = (b*8+h)*1024 + t
    int d = tid & 31;
    int b = r >> 13;
    int h = (r >> 10) & 7;
    int t = r & 1023;
    Xs[tid >> 5][d] = src[((size_t)(b * LL + t)) * DIMM + h * 32 + d];
    __syncthreads();

    float acc = 0.f;
    #pragma unroll
    for (int dp = 0; dp < 32; dp++) acc += Xs[tid >> 5][dp] * Ws[dp * 32 + d];
    dst[(size_t)r * 32 + d] = acc;
}

// ---------------------------------------------------------------------------
// Generic per-(b,h) SGEMM:  C[l,d] = sum_t Amat[bh][l,t] * Bm[bh][t,d]
// ---------------------------------------------------------------------------
__global__ __launch_bounds__(256) void gemm_adj(
    const float* __restrict__ Amat, const float* __restrict__ Bm,
    float* __restrict__ C, size_t c_b_stride, size_t c_h_stride, int c_row_stride)
{
    __shared__ float Ast[32][68];
    __shared__ float Bs[1024];

    int tid = threadIdx.x;
    int bh = blockIdx.y;
    const float* A  = Amat + (size_t)bh * (LL * LL);
    const float* Bb = Bm + (size_t)bh * (LL * DD);
    float* Cb = C + (size_t)(bh >> 3) * c_b_stride + (size_t)(bh & 7) * c_h_stride;
    int l0 = blockIdx.x * 64;

    int d = tid & 31, rg = tid >> 5;
    int lrow = tid >> 2, cseg = (tid & 3) * 8;

    float acc[8] = {0.f,0.f,0.f,0.f,0.f,0.f,0.f,0.f};

    for (int k0 = 0; k0 < LL; k0 += 32) {
        const float* arow = A + (size_t)(l0 + lrow) * LL + k0 + cseg;
        float4 a0 = *(const float4*)(arow);
        float4 a1 = *(const float4*)(arow + 4);
        Ast[cseg+0][lrow] = a0.x; Ast[cseg+1][lrow] = a0.y;
        Ast[cseg+2][lrow] = a0.z; Ast[cseg+3][lrow] = a0.w;
        Ast[cseg+4][lrow] = a1.x; Ast[cseg+5][lrow] = a1.y;
        Ast[cseg+6][lrow] = a1.z; Ast[cseg+7][lrow] = a1.w;
        *(float4*)&Bs[tid * 4] = *(const float4*)(Bb + (size_t)k0 * 32 + tid * 4);
        __syncthreads();

        #pragma unroll
        for (int kk = 0; kk < 32; kk++) {
            float bv = Bs[kk * 32 + d];
            float4 av0 = *(const float4*)&Ast[kk][rg * 8];
            float4 av1 = *(const float4*)&Ast[kk][rg * 8 + 4];
            acc[0] += av0.x * bv; acc[1] += av0.y * bv;
            acc[2] += av0.z * bv; acc[3] += av0.w * bv;
            acc[4] += av1.x * bv; acc[5] += av1.y * bv;
            acc[6] += av1.z * bv; acc[7] += av1.w * bv;
        }
        __syncthreads();
    }
    #pragma unroll
    for (int j = 0; j < 8; j++)
        Cb[(size_t)(l0 + rg * 8 + j) * c_row_stride + d] = acc[j];
}

// ---------------------------------------------------------------------------
// K3 (single pass): logits + leaky + R head-mixing + mask.
// Writes raw masked mixed logits m (or -inf) to M_out (the A buffer) and
// per-row softmax stats (max, 1/sum) to scratch. Double-buffered Ss: one
// __syncthreads per 32-t chunk. Deterministic warp-shuffle reductions.
// ---------------------------------------------------------------------------
__global__ __launch_bounds__(256) void attn_logits_kernel(
    const float* __restrict__ q, const float* __restrict__ k,
    const float* __restrict__ adj, const float* __restrict__ R,
    float* __restrict__ M_out, float* __restrict__ rmax_out,
    float* __restrict__ rinv_out)
{
    __shared__ float Qs[8][8][32];
    __shared__ float Ss[2][8][8][32];
    __shared__ float Rs[64];

    int tid = threadIdx.x, w = tid >> 5, lane = tid & 31;
    int b = blockIdx.y, l0 = blockIdx.x * 8;

    for (int i = tid; i < 2048; i += 256) {
        int h = i >> 8, li = (i >> 5) & 7, d = i & 31;
        Qs[h][li][d] = q[((size_t)((b * 8 + h) * LL + l0 + li)) * 32 + d];
    }
    if (tid < 64) Rs[tid] = R[tid];

    float rmax[8], rsum[8];
    #pragma unroll
    for (int i = 0; i < 8; i++) { rmax[i] = -INFINITY; rsum[i] = 0.f; }
    __syncthreads();

    const int l = l0 + w;
    const float* kb = k + ((size_t)((b * 8 + w) * LL + lane)) * 32;  // head w, row lane

    for (int c = 0; c < 32; c++) {
        int t0 = c * 32;
        int buf = c & 1;
        // phase A: logits for head h = w; lane covers t = t0 + lane; 8 l rows
        {
            const float* krow = kb + (size_t)t0 * 32;
            float acc[8] = {0.f,0.f,0.f,0.f,0.f,0.f,0.f,0.f};
            #pragma unroll
            for (int d4 = 0; d4 < 32; d4 += 4) {
                float4 kv = *(const float4*)(krow + d4);
                #pragma unroll
                for (int li = 0; li < 8; li++) {
                    float4 qv = *(const float4*)&Qs[w][li][d4];
                    acc[li] += qv.x*kv.x + qv.y*kv.y + qv.z*kv.z + qv.w*kv.w;
                }
            }
            #pragma unroll
            for (int li = 0; li < 8; li++) {
                float s = acc[li] * ATT_SCALE;
                Ss[buf][w][li][lane] = (s > 0.f) ? s : 0.01f * s;   // leaky_relu
            }
        }
        __syncthreads();

        // phase B: mixing + mask + online stats for row li = w
        {
            float sv[8];
            #pragma unroll
            for (int h = 0; h < 8; h++) sv[h] = Ss[buf][h][w][lane];
            int t = t0 + lane;
            #pragma unroll
            for (int i = 0; i < 8; i++) {
                float m = 0.f;
                #pragma unroll
                for (int h = 0; h < 8; h++) m += Rs[i * 8 + h] * sv[h];
                size_t idx = ((size_t)((b * 8 + i) * LL + l)) * LL + t;
                float a = adj[idx];
                if (a > 0.f) {
                    float nm = fmaxf(rmax[i], m);
                    rsum[i] = rsum[i] * __expf(rmax[i] - nm) + __expf(m - nm);
                    rmax[i] = nm;
                    M_out[idx] = m;
                } else {
                    M_out[idx] = -INFINITY;
                }
            }
        }
        // no second sync: next phase A writes the other Ss buffer
    }

    // combine online (max,sum) across the 32 lanes of each warp; write stats
    #pragma unroll
    for (int i = 0; i < 8; i++) {
        float mx = rmax[i], sm = rsum[i];
        #pragma unroll
        for (int off = 16; off; off >>= 1) {
            float om = __shfl_down_sync(0xffffffffu, mx, off);
            float os = __shfl_down_sync(0xffffffffu, sm, off);
            float nm = fmaxf(mx, om);
            float p1 = (sm > 0.f) ? sm * __expf(mx - nm) : 0.f;
            float p2 = (os > 0.f) ? os * __expf(om - nm) : 0.f;
            mx = nm; sm = p1 + p2;
        }
        if (lane == 0) {
            int sidx = (b * 8 + i) * LL + l;
            rmax_out[sidx] = mx;
            rinv_out[sidx] = 1.f / sm;   // diagonal always unmasked -> sm >= 1 term
        }
    }
}

// ---------------------------------------------------------------------------
// K4: normalize + transposed-softmax column sums, fused single pass.
// Reads raw logits m from A, writes A = exp(m - rmax[l]) * rinv[l]
// (masked m = -inf -> 0), accumulates rcol[t] = 1 / sum_l exp(A[l,t]).
// ---------------------------------------------------------------------------
__global__ __launch_bounds__(256) void norm_colsum_kernel(
    float* __restrict__ A, const float* __restrict__ rmax,
    const float* __restrict__ rinv, float* __restrict__ rcol)
{
    int bi = blockIdx.y;
    int t = blockIdx.x * 256 + threadIdx.x;
    float* base = A + (size_t)bi * (LL * LL);
    const float* mx = rmax + bi * LL;
    const float* iv = rinv + bi * LL;

    float s0 = 0.f, s1 = 0.f, s2 = 0.f, s3 = 0.f;
    for (int lr = 0; lr < LL; lr += 4) {
        float m0 = base[(size_t)(lr + 0) * LL + t];
        float m1 = base[(size_t)(lr + 1) * LL + t];
        float m2 = base[(size_t)(lr + 2) * LL + t];
        float m3 = base[(size_t)(lr + 3) * LL + t];
        float a0 = __expf(m0 - mx[lr + 0]) * iv[lr + 0];
        float a1 = __expf(m1 - mx[lr + 1]) * iv[lr + 1];
        float a2 = __expf(m2 - mx[lr + 2]) * iv[lr + 2];
        float a3 = __expf(m3 - mx[lr + 3]) * iv[lr + 3];
        base[(size_t)(lr + 0) * LL + t] = a0;
        base[(size_t)(lr + 1) * LL + t] = a1;
        base[(size_t)(lr + 2) * LL + t] = a2;
        base[(size_t)(lr + 3) * LL + t] = a3;
        s0 += __expf(a0); s1 += __expf(a1);
        s2 += __expf(a2); s3 += __expf(a3);
    }
    rcol[bi * LL + t] = 1.f / ((s0 + s1) + (s2 + s3));
}

// ---------------------------------------------------------------------------
// K5: Ar[b,i,t,l] = exp(A[b,i,l,t]) * rcol[b,i,t]   (tiled transpose)
// ---------------------------------------------------------------------------
__global__ __launch_bounds__(256) void transpose_exp_kernel(
    const float* __restrict__ A, const float* __restrict__ rcol,
    float* __restrict__ Ar)
{
    __shared__ float Ts[32][33];
    int bi = blockIdx.z;
    int l0 = blockIdx.x * 32, t0 = blockIdx.y * 32;
    int lane = threadIdx.x & 31, wr = threadIdx.x >> 5;
    const float* base = A + (size_t)bi * (LL * LL);
    float* obase = Ar + (size_t)bi * (LL * LL);
    #pragma unroll
    for (int j = 0; j < 4; j++) {
        int lr = wr + j * 8;
        Ts[lr][lane] = base[(size_t)(l0 + lr) * LL + t0 + lane];
    }
    __syncthreads();
    #pragma unroll
    for (int j = 0; j < 4; j++) {
        int tr = wr + j * 8;
        float rc = rcol[bi * LL + t0 + tr];
        obase[(size_t)(t0 + tr) * LL + l0 + lane] = __expf(Ts[lane][tr]) * rc;
    }
}

// ---------------------------------------------------------------------------
// K6: Out[r,n] = sum_m gelu(Vm[r,m]) * Wp[m,n]   (exact gelu, erf)
// ---------------------------------------------------------------------------
__device__ __forceinline__ float gelu_exact(float v)
{
    return 0.5f * v * (1.f + erff(v * 0.70710678118654752f));
}

__global__ __launch_bounds__(256) void out_gemm(
    const float* __restrict__ Vm, const float* __restrict__ Wp,
    float* __restrict__ Out)
{
    __shared__ float Gs[32][68];
    __shared__ float Ws[1024];
    int tid = threadIdx.x;
    int r0 = blockIdx.x * 64, n0 = blockIdx.y * 32;
    int d = tid & 31, rg = tid >> 5;
    int rrow = tid >> 2, cseg = (tid & 3) * 8;

    float acc[8] = {0.f,0.f,0.f,0.f,0.f,0.f,0.f,0.f};

    for (int k0 = 0; k0 < DIMM; k0 += 32) {
        const float* vrow = Vm + (size_t)(r0 + rrow) * DIMM + k0 + cseg;
        float4 a0 = *(const float4*)(vrow);
        float4 a1 = *(const float4*)(vrow + 4);
        Gs[cseg+0][rrow] = gelu_exact(a0.x); Gs[cseg+1][rrow] = gelu_exact(a0.y);
        Gs[cseg+2][rrow] = gelu_exact(a0.z); Gs[cseg+3][rrow] = gelu_exact(a0.w);
        Gs[cseg+4][rrow] = gelu_exact(a1.x); Gs[cseg+5][rrow] = gelu_exact(a1.y);
        Gs[cseg+6][rrow] = gelu_exact(a1.z); Gs[cseg+7][rrow] = gelu_exact(a1.w);
        *(float4*)&Ws[(tid >> 3) * 32 + (tid & 7) * 4] =
            *(const float4*)(Wp + (size_t)(k0 + (tid >> 3)) * DIMM + n0 + (tid & 7) * 4);
        __syncthreads();

        #pragma unroll
        for (int kk = 0; kk < 32; kk++) {
            float bv = Ws[kk * 32 + d];
            float4 av0 = *(const float4*)&Gs[kk][rg * 8];
            float4 av1 = *(const float4*)&Gs[kk][rg * 8 + 4];
            acc[0] += av0.x * bv; acc[1] += av0.y * bv;
            acc[2] += av0.z * bv; acc[3] += av0.w * bv;
            acc[4] += av1.x * bv; acc[5] += av1.y * bv;
            acc[6] += av1.z * bv; acc[7] += av1.w * bv;
        }
        __syncthreads();
    }
    #pragma unroll
    for (int j = 0; j < 8; j++)
        Out[(size_t)(r0 + rg * 8 + j) * DIMM + n0 + d] = acc[j];
}

// ---------------------------------------------------------------------------
// Launch. Output layout (float32, concatenated in reference return order):
//   out [4,1024,256] | out_resize [4,1024,256] | A [4,8,1024,1024] | Ar [...]
// ---------------------------------------------------------------------------
extern "C" void kernel_launch(void* const* d_in, const int* in_sizes, int n_in,
                              void* d_out, int out_size)
{
    const float* x    = (const float*)d_in[0];
    const float* rx   = (const float*)d_in[1];
    const float* adj  = (const float*)d_in[2];
    const float* adjr = (const float*)d_in[3];
    const float* Wq   = (const float*)d_in[4];
    const float* Wk   = (const float*)d_in[5];
    const float* Wv   = (const float*)d_in[6];
    const float* R    = (const float*)d_in[7];
    const float* Wp   = (const float*)d_in[8];

    float* out  = (float*)d_out;
    float* outr = out + (size_t)BB * LL * DIMM;            // 1048576
    float* A    = out + (size_t)2 * BB * LL * DIMM;        // 2097152
    float* Ar   = A + (size_t)BB * HH * LL * LL;           // 35651584

    float* s = nullptr;
    cudaGetSymbolAddress((void**)&s, g_scratch);

    // K1: projections (xq, xk, xv, rv)
    proj_kernel<<<dim3(4096, 4), 256>>>(x, rx, Wq, Wk, Wv, s);

    // K2: q = adj @ xq ; k = adj_resize @ xk   -> [b,h,l,d] scratch
    gemm_adj<<<dim3(16, 32), 256>>>(adj,  s + OFF_XQ, s + OFF_Q,
                                    (size_t)HH * LL * DD, (size_t)LL * DD, DD);
    gemm_adj<<<dim3(16, 32), 256>>>(adjr, s + OFF_XK, s + OFF_K,
                                    (size_t)HH * LL * DD, (size_t)LL * DD, DD);

    // K3: single-pass logits + mask -> raw m in A buffer; stats to scratch
    attn_logits_kernel<<<dim3(128, 4), 256>>>(s + OFF_Q, s + OFF_K, adj, R, A,
                                              s + OFF_RMAX, s + OFF_RINV);

    // K4: normalize A in place + transposed-softmax column sums
    norm_colsum_kernel<<<dim3(4, 32), 256>>>(A, s + OFF_RMAX, s + OFF_RINV,
                                             s + OFF_RCOL);

    // K5: dual softmax on transpose -> Ar
    transpose_exp_kernel<<<dim3(32, 32, 32), 256>>>(A, s + OFF_RCOL, Ar);

    // v = A @ xv ; vr = Ar @ rv   -> merged [b, l, h*32+d] layout
    gemm_adj<<<dim3(16, 32), 256>>>(A,  s + OFF_XV, s + OFF_VM,
                                    (size_t)LL * DIMM, (size_t)DD, DIMM);
    gemm_adj<<<dim3(16, 32), 256>>>(Ar, s + OFF_RV, s + OFF_VRM,
                                    (size_t)LL * DIMM, (size_t)DD, DIMM);

    // K6: out = gelu(v) @ Wp ; out_resize = gelu(vr) @ Wp
    out_gemm<<<dim3(64, 8), 256>>>(s + OFF_VM,  Wp, out);
    out_gemm<<<dim3(64, 8), 256>>>(s + OFF_VRM, Wp, outr);
}

// round 5
// speedup vs baseline: 1.6387x; 1.2422x over previous
#include <cuda_runtime.h>
#include <math.h>

#define BB 4
#define HH 8
#define LL 1024
#define DD 32
#define DIMM 256
#define ATT_SCALE 0.0625f   // DIM^-0.5 = 1/16

#define M1 1048576
// scratch layout (floats)
#define OFF_XQ  (0*M1)
#define OFF_XK  (1*M1)
#define OFF_XV  (2*M1)
#define OFF_RV  (3*M1)
#define OFF_Q   (4*M1)
#define OFF_K   (5*M1)
#define OFF_VM  (6*M1)
#define OFF_VRM (7*M1)
#define OFF_RCOL (8*M1)
#define OFF_RMAX (8*M1 + 32768)
#define OFF_RINV (8*M1 + 65536)

__device__ float g_scratch[8*M1 + 3*32768];

// packed fp32x2 helpers (sm_100+)
#define FMA2(acc, a, b) \
    asm("fma.rn.f32x2 %0, %1, %2, %0;" : "+l"(acc) : "l"(a), "l"(b))
#define DUP2(dst, v) \
    asm("mov.b64 %0, {%1, %1};" : "=l"(dst) : "f"(v))
#define UNPACK2(lo, hi, v) \
    asm("mov.b64 {%0, %1}, %2;" : "=f"(lo), "=f"(hi) : "l"(v))

// ---------------------------------------------------------------------------
// K1: per-head projections  dst[b,h,t,d] = sum_dp src[b,t,h*32+dp] * W[dp,d]
// ---------------------------------------------------------------------------
__global__ __launch_bounds__(256) void proj_kernel(
    const float* __restrict__ x, const float* __restrict__ rx,
    const float* __restrict__ Wq, const float* __restrict__ Wk,
    const float* __restrict__ Wv, float* __restrict__ scratch)
{
    int tid = threadIdx.x;
    int which = blockIdx.y;
    const float* src = (which == 0 || which == 2) ? x : rx;
    const float* W = (which == 0) ? Wq : ((which == 1) ? Wk : Wv);
    float* dst = scratch + (size_t)which * M1;

    __shared__ float Ws[1024];
    __shared__ float Xs[8][32];
    for (int i = tid; i < 1024; i += 256) Ws[i] = W[i];

    int r = blockIdx.x * 8 + (tid >> 5);   // r = (b*8+h)*1024 + t
    int d = tid & 31;
    int b = r >> 13;
    int h = (r >> 10) & 7;
    int t = r & 1023;
    Xs[tid >> 5][d] = src[((size_t)(b * LL + t)) * DIMM + h * 32 + d];
    __syncthreads();

    float acc = 0.f;
    #pragma unroll
    for (int dp = 0; dp < 32; dp++) acc += Xs[tid >> 5][dp] * Ws[dp * 32 + d];
    dst[(size_t)r * 32 + d] = acc;
}

// ---------------------------------------------------------------------------
// K2: per-(b,h) SGEMM  C[l,d] = sum_t Amat[bh][l,t] * Bm[bh][t,d]
// 128x32 tile, K-chunk 32, 256 threads, 16 outputs/thread, packed f32x2 FMA,
// register prefetch. blockIdx.z selects between two (A,B,C) problem sets.
// ---------------------------------------------------------------------------
__global__ __launch_bounds__(256) void gemm_adj(
    const float* __restrict__ A0, const float* __restrict__ B0, float* __restrict__ C0,
    const float* __restrict__ A1, const float* __restrict__ B1, float* __restrict__ C1,
    size_t c_b_stride, size_t c_h_stride, int c_row_stride)
{
    __shared__ float Ast[32][132];   // transposed A tile [k][row]
    __shared__ float Bs[1024];       // [k][d]

    int tid = threadIdx.x;
    int bh = blockIdx.y;
    const float* A  = (blockIdx.z ? A1 : A0) + (size_t)bh * (LL * LL);
    const float* Bb = (blockIdx.z ? B1 : B0) + (size_t)bh * (LL * DD);
    float* Cb = (blockIdx.z ? C1 : C0)
              + (size_t)(bh >> 3) * c_b_stride + (size_t)(bh & 7) * c_h_stride;
    int l0 = blockIdx.x * 128;

    int d = tid & 31, rg = tid >> 5;            // 16 rows rg*16..rg*16+15, col d
    int lrow = tid >> 1, cseg = (tid & 1) * 16; // staging: half-row per thread

    unsigned long long acc2[8];
    #pragma unroll
    for (int j = 0; j < 8; j++) acc2[j] = 0ULL;

    float4 pa0, pa1, pa2, pa3, pb;
    {
        const float* p = A + (size_t)(l0 + lrow) * LL + cseg;
        pa0 = *(const float4*)(p);      pa1 = *(const float4*)(p + 4);
        pa2 = *(const float4*)(p + 8);  pa3 = *(const float4*)(p + 12);
        pb  = *(const float4*)(Bb + tid * 4);
    }

    for (int c = 0; c < 32; c++) {
        Ast[cseg+ 0][lrow]=pa0.x; Ast[cseg+ 1][lrow]=pa0.y;
        Ast[cseg+ 2][lrow]=pa0.z; Ast[cseg+ 3][lrow]=pa0.w;
        Ast[cseg+ 4][lrow]=pa1.x; Ast[cseg+ 5][lrow]=pa1.y;
        Ast[cseg+ 6][lrow]=pa1.z; Ast[cseg+ 7][lrow]=pa1.w;
        Ast[cseg+ 8][lrow]=pa2.x; Ast[cseg+ 9][lrow]=pa2.y;
        Ast[cseg+10][lrow]=pa2.z; Ast[cseg+11][lrow]=pa2.w;
        Ast[cseg+12][lrow]=pa3.x; Ast[cseg+13][lrow]=pa3.y;
        Ast[cseg+14][lrow]=pa3.z; Ast[cseg+15][lrow]=pa3.w;
        *(float4*)&Bs[tid * 4] = pb;
        __syncthreads();

        if (c < 31) {
            int k0 = (c + 1) * 32;
            const float* p = A + (size_t)(l0 + lrow) * LL + k0 + cseg;
            pa0 = *(const float4*)(p);      pa1 = *(const float4*)(p + 4);
            pa2 = *(const float4*)(p + 8);  pa3 = *(const float4*)(p + 12);
            pb  = *(const float4*)(Bb + (size_t)k0 * DD + tid * 4);
        }

        #pragma unroll
        for (int kk = 0; kk < 32; kk++) {
            float bv = Bs[kk * 32 + d];
            unsigned long long bvv;
            DUP2(bvv, bv);
            const ulonglong2* ap = (const ulonglong2*)&Ast[kk][rg * 16];
            ulonglong2 q0 = ap[0];   // rows +0,+1,+2,+3
            ulonglong2 q1 = ap[1];   // rows +4..+7
            ulonglong2 q2 = ap[2];
            ulonglong2 q3 = ap[3];
            FMA2(acc2[0], q0.x, bvv); FMA2(acc2[1], q0.y, bvv);
            FMA2(acc2[2], q1.x, bvv); FMA2(acc2[3], q1.y, bvv);
            FMA2(acc2[4], q2.x, bvv); FMA2(acc2[5], q2.y, bvv);
            FMA2(acc2[6], q3.x, bvv); FMA2(acc2[7], q3.y, bvv);
        }
        __syncthreads();
    }

    #pragma unroll
    for (int j = 0; j < 8; j++) {
        float lo, hi;
        UNPACK2(lo, hi, acc2[j]);
        Cb[(size_t)(l0 + rg * 16 + 2*j    ) * c_row_stride + d] = lo;
        Cb[(size_t)(l0 + rg * 16 + 2*j + 1) * c_row_stride + d] = hi;
    }
}

// ---------------------------------------------------------------------------
// K3: logits + leaky + R head-mixing + mask -> raw logits (or -inf) in M_out;
// per-row max to rmax_out. K staged through smem (coalesced, conflict-free
// pad-36). No exp in the hot loop. Dynamic smem (53.5 KB).
// ---------------------------------------------------------------------------
struct AttnSmem {
    float Qs[8][8][32];
    float Ss[8][8][32];
    float Ks[8][32][36];
    float Rs[64];
};

extern __shared__ unsigned char attn_smem_raw[];

__global__ __launch_bounds__(256) void attn_logits_kernel(
    const float* __restrict__ q, const float* __restrict__ k,
    const float* __restrict__ adj, const float* __restrict__ R,
    float* __restrict__ M_out, float* __restrict__ rmax_out)
{
    AttnSmem* S = (AttnSmem*)attn_smem_raw;
    int tid = threadIdx.x, w = tid >> 5, lane = tid & 31;
    int b = blockIdx.y, l0 = blockIdx.x * 8;

    for (int i = tid; i < 2048; i += 256) {
        int h = i >> 8, li = (i >> 5) & 7, d = i & 31;
        S->Qs[h][li][d] = q[((size_t)((b * 8 + h) * LL + l0 + li)) * 32 + d];
    }
    if (tid < 64) S->Rs[tid] = R[tid];

    float rmax[8];
    #pragma unroll
    for (int i = 0; i < 8; i++) rmax[i] = -INFINITY;
    __syncthreads();

    const int l = l0 + w;
    const float* kbase = k + (size_t)(b * 8 + w) * (LL * DD);  // head w

    for (int t0 = 0; t0 < LL; t0 += 32) {
        // stage K chunk (warp w loads head w's rows t0..t0+31, coalesced)
        #pragma unroll
        for (int j = 0; j < 8; j++) {
            int fi = j * 32 + lane;
            int t = fi >> 3, d4 = (fi & 7) * 4;
            *(float4*)&S->Ks[w][t][d4] =
                *(const float4*)(kbase + (size_t)(t0 + t) * DD + d4);
        }
        __syncthreads();

        // phase A: logits for head w; lane covers t = t0 + lane; 8 l rows
        {
            float acc[8] = {0.f,0.f,0.f,0.f,0.f,0.f,0.f,0.f};
            #pragma unroll
            for (int d4 = 0; d4 < 32; d4 += 4) {
                float4 kv = *(const float4*)&S->Ks[w][lane][d4];
                #pragma unroll
                for (int li = 0; li < 8; li++) {
                    float4 qv = *(const float4*)&S->Qs[w][li][d4];
                    acc[li] += qv.x*kv.x + qv.y*kv.y + qv.z*kv.z + qv.w*kv.w;
                }
            }
            #pragma unroll
            for (int li = 0; li < 8; li++) {
                float s = acc[li] * ATT_SCALE;
                S->Ss[w][li][lane] = (s > 0.f) ? s : 0.01f * s;   // leaky_relu
            }
        }
        __syncthreads();

        // phase B: mixing + mask + running max for row li = w
        {
            float sv[8];
            #pragma unroll
            for (int h = 0; h < 8; h++) sv[h] = S->Ss[h][w][lane];
            int t = t0 + lane;
            #pragma unroll
            for (int i = 0; i < 8; i++) {
                float m = 0.f;
                #pragma unroll
                for (int h = 0; h < 8; h++) m += S->Rs[i * 8 + h] * sv[h];
                size_t idx = ((size_t)((b * 8 + i) * LL + l)) * LL + t;
                float a = adj[idx];
                float o = (a > 0.f) ? m : -INFINITY;
                M_out[idx] = o;
                rmax[i] = fmaxf(rmax[i], o);
            }
        }
        // next staging is safe: phase A's Ks reads completed before prior sync
    }

    // warp max-reduce per i; lane 0 writes
    #pragma unroll
    for (int i = 0; i < 8; i++) {
        float mx = rmax[i];
        #pragma unroll
        for (int off = 16; off; off >>= 1)
            mx = fmaxf(mx, __shfl_down_sync(0xffffffffu, mx, off));
        if (lane == 0) rmax_out[(b * 8 + i) * LL + l] = mx;
    }
}

// ---------------------------------------------------------------------------
// K3b: rinv[row] = 1 / sum_t exp(M[row,t] - rmax[row])   (coalesced row pass)
// masked entries are -inf -> exp = 0.
// ---------------------------------------------------------------------------
__global__ __launch_bounds__(256) void rowsum_kernel(
    const float* __restrict__ M, const float* __restrict__ rmax,
    float* __restrict__ rinv)
{
    int row = blockIdx.x * 8 + (threadIdx.x >> 5);
    int lane = threadIdx.x & 31;
    const float* r = M + (size_t)row * LL;
    float mx = rmax[row];
    float sum = 0.f;
    #pragma unroll
    for (int j = 0; j < 8; j++) {
        float4 v = *(const float4*)(r + (j * 32 + lane) * 4);
        sum += __expf(v.x - mx) + __expf(v.y - mx)
             + __expf(v.z - mx) + __expf(v.w - mx);
    }
    #pragma unroll
    for (int off = 16; off; off >>= 1)
        sum += __shfl_down_sync(0xffffffffu, sum, off);
    if (lane == 0) rinv[row] = 1.f / sum;
}

// ---------------------------------------------------------------------------
// K4: normalize A in place + transposed-softmax column sums.
// ---------------------------------------------------------------------------
__global__ __launch_bounds__(256) void norm_colsum_kernel(
    float* __restrict__ A, const float* __restrict__ rmax,
    const float* __restrict__ rinv, float* __restrict__ rcol)
{
    int bi = blockIdx.y;
    int t = blockIdx.x * 256 + threadIdx.x;
    float* base = A + (size_t)bi * (LL * LL);
    const float* mx = rmax + bi * LL;
    const float* iv = rinv + bi * LL;

    float s0 = 0.f, s1 = 0.f, s2 = 0.f, s3 = 0.f;
    for (int lr = 0; lr < LL; lr += 4) {
        float m0 = base[(size_t)(lr + 0) * LL + t];
        float m1 = base[(size_t)(lr + 1) * LL + t];
        float m2 = base[(size_t)(lr + 2) * LL + t];
        float m3 = base[(size_t)(lr + 3) * LL + t];
        float a0 = __expf(m0 - mx[lr + 0]) * iv[lr + 0];
        float a1 = __expf(m1 - mx[lr + 1]) * iv[lr + 1];
        float a2 = __expf(m2 - mx[lr + 2]) * iv[lr + 2];
        float a3 = __expf(m3 - mx[lr + 3]) * iv[lr + 3];
        base[(size_t)(lr + 0) * LL + t] = a0;
        base[(size_t)(lr + 1) * LL + t] = a1;
        base[(size_t)(lr + 2) * LL + t] = a2;
        base[(size_t)(lr + 3) * LL + t] = a3;
        s0 += __expf(a0); s1 += __expf(a1);
        s2 += __expf(a2); s3 += __expf(a3);
    }
    rcol[bi * LL + t] = 1.f / ((s0 + s1) + (s2 + s3));
}

// ---------------------------------------------------------------------------
// K5: Ar[b,i,t,l] = exp(A[b,i,l,t]) * rcol[b,i,t]   (tiled transpose)
// ---------------------------------------------------------------------------
__global__ __launch_bounds__(256) void transpose_exp_kernel(
    const float* __restrict__ A, const float* __restrict__ rcol,
    float* __restrict__ Ar)
{
    __shared__ float Ts[32][33];
    int bi = blockIdx.z;
    int l0 = blockIdx.x * 32, t0 = blockIdx.y * 32;
    int lane = threadIdx.x & 31, wr = threadIdx.x >> 5;
    const float* base = A + (size_t)bi * (LL * LL);
    float* obase = Ar + (size_t)bi * (LL * LL);
    #pragma unroll
    for (int j = 0; j < 4; j++) {
        int lr = wr + j * 8;
        Ts[lr][lane] = base[(size_t)(l0 + lr) * LL + t0 + lane];
    }
    __syncthreads();
    #pragma unroll
    for (int j = 0; j < 4; j++) {
        int tr = wr + j * 8;
        float rc = rcol[bi * LL + t0 + tr];
        obase[(size_t)(t0 + tr) * LL + l0 + lane] = __expf(Ts[lane][tr]) * rc;
    }
}

// ---------------------------------------------------------------------------
// K6: Out[r,n] = sum_m gelu(Vm[r,m]) * Wp[m,n], packed f32x2 inner loop.
// blockIdx.z selects (Vm, Out) pair.
// ---------------------------------------------------------------------------
__device__ __forceinline__ float gelu_exact(float v)
{
    return 0.5f * v * (1.f + erff(v * 0.70710678118654752f));
}

__global__ __launch_bounds__(256) void out_gemm(
    const float* __restrict__ V0, const float* __restrict__ V1,
    const float* __restrict__ Wp,
    float* __restrict__ O0, float* __restrict__ O1)
{
    __shared__ float Gs[32][68];
    __shared__ float Ws[1024];
    const float* Vm = blockIdx.z ? V1 : V0;
    float* Out = blockIdx.z ? O1 : O0;
    int tid = threadIdx.x;
    int r0 = blockIdx.x * 64, n0 = blockIdx.y * 32;
    int d = tid & 31, rg = tid >> 5;
    int rrow = tid >> 2, cseg = (tid & 3) * 8;

    unsigned long long acc2[4];
    #pragma unroll
    for (int j = 0; j < 4; j++) acc2[j] = 0ULL;

    for (int k0 = 0; k0 < DIMM; k0 += 32) {
        const float* vrow = Vm + (size_t)(r0 + rrow) * DIMM + k0 + cseg;
        float4 a0 = *(const float4*)(vrow);
        float4 a1 = *(const float4*)(vrow + 4);
        Gs[cseg+0][rrow] = gelu_exact(a0.x); Gs[cseg+1][rrow] = gelu_exact(a0.y);
        Gs[cseg+2][rrow] = gelu_exact(a0.z); Gs[cseg+3][rrow] = gelu_exact(a0.w);
        Gs[cseg+4][rrow] = gelu_exact(a1.x); Gs[cseg+5][rrow] = gelu_exact(a1.y);
        Gs[cseg+6][rrow] = gelu_exact(a1.z); Gs[cseg+7][rrow] = gelu_exact(a1.w);
        *(float4*)&Ws[(tid >> 3) * 32 + (tid & 7) * 4] =
            *(const float4*)(Wp + (size_t)(k0 + (tid >> 3)) * DIMM + n0 + (tid & 7) * 4);
        __syncthreads();

        #pragma unroll
        for (int kk = 0; kk < 32; kk++) {
            float bv = Ws[kk * 32 + d];
            unsigned long long bvv;
            DUP2(bvv, bv);
            const ulonglong2* gp = (const ulonglong2*)&Gs[kk][rg * 8];
            ulonglong2 g0 = gp[0];
            ulonglong2 g1 = gp[1];
            FMA2(acc2[0], g0.x, bvv); FMA2(acc2[1], g0.y, bvv);
            FMA2(acc2[2], g1.x, bvv); FMA2(acc2[3], g1.y, bvv);
        }
        __syncthreads();
    }
    #pragma unroll
    for (int j = 0; j < 4; j++) {
        float lo, hi;
        UNPACK2(lo, hi, acc2[j]);
        Out[(size_t)(r0 + rg * 8 + 2*j    ) * DIMM + n0 + d] = lo;
        Out[(size_t)(r0 + rg * 8 + 2*j + 1) * DIMM + n0 + d] = hi;
    }
}

// ---------------------------------------------------------------------------
// Launch. Output layout (float32, reference return order):
//   out [4,1024,256] | out_resize [4,1024,256] | A [4,8,1024,1024] | Ar [...]
// ---------------------------------------------------------------------------
extern "C" void kernel_launch(void* const* d_in, const int* in_sizes, int n_in,
                              void* d_out, int out_size)
{
    const float* x    = (const float*)d_in[0];
    const float* rx   = (const float*)d_in[1];
    const float* adj  = (const float*)d_in[2];
    const float* adjr = (const float*)d_in[3];
    const float* Wq   = (const float*)d_in[4];
    const float* Wk   = (const float*)d_in[5];
    const float* Wv   = (const float*)d_in[6];
    const float* R    = (const float*)d_in[7];
    const float* Wp   = (const float*)d_in[8];

    float* out  = (float*)d_out;
    float* outr = out + (size_t)BB * LL * DIMM;
    float* A    = out + (size_t)2 * BB * LL * DIMM;
    float* Ar   = A + (size_t)BB * HH * LL * LL;

    float* s = nullptr;
    cudaGetSymbolAddress((void**)&s, g_scratch);

    cudaFuncSetAttribute(attn_logits_kernel,
                         cudaFuncAttributeMaxDynamicSharedMemorySize,
                         (int)sizeof(AttnSmem));

    // K1: projections (xq, xk, xv, rv)
    proj_kernel<<<dim3(4096, 4), 256>>>(x, rx, Wq, Wk, Wv, s);

    // K2: q = adj @ xq (z=0) ; k = adj_resize @ xk (z=1)
    gemm_adj<<<dim3(8, 32, 2), 256>>>(adj,  s + OFF_XQ, s + OFF_Q,
                                      adjr, s + OFF_XK, s + OFF_K,
                                      (size_t)HH * LL * DD, (size_t)LL * DD, DD);

    // K3: logits + mask -> raw m in A buffer; row max to scratch
    attn_logits_kernel<<<dim3(128, 4), 256, sizeof(AttnSmem)>>>(
        s + OFF_Q, s + OFF_K, adj, R, A, s + OFF_RMAX);

    // K3b: row sums -> rinv
    rowsum_kernel<<<4096, 256>>>(A, s + OFF_RMAX, s + OFF_RINV);

    // K4: normalize A in place + transposed-softmax column sums
    norm_colsum_kernel<<<dim3(4, 32), 256>>>(A, s + OFF_RMAX, s + OFF_RINV,
                                             s + OFF_RCOL);

    // K5: dual softmax on transpose -> Ar
    transpose_exp_kernel<<<dim3(32, 32, 32), 256>>>(A, s + OFF_RCOL, Ar);

    // v = A @ xv (z=0) ; vr = Ar @ rv (z=1) -> merged [b, l, h*32+d]
    gemm_adj<<<dim3(8, 32, 2), 256>>>(A,  s + OFF_XV, s + OFF_VM,
                                      Ar, s + OFF_RV, s + OFF_VRM,
                                      (size_t)LL * DIMM, (size_t)DD, DIMM);

    // K6: out = gelu(v) @ Wp ; out_resize = gelu(vr) @ Wp
    out_gemm<<<dim3(64, 8, 2), 256>>>(s + OFF_VM, s + OFF_VRM, Wp, out, outr);
}

// round 6
// speedup vs baseline: 1.8896x; 1.1531x over previous
#include <cuda_runtime.h>
#include <math.h>

#define BB 4
#define HH 8
#define LL 1024
#define DD 32
#define DIMM 256
#define ATT_SCALE 0.0625f   // DIM^-0.5 = 1/16

#define M1 1048576
// scratch layout (floats)
#define OFF_XQ  (0*M1)
#define OFF_XK  (1*M1)
#define OFF_XV  (2*M1)
#define OFF_RV  (3*M1)
#define OFF_Q   (4*M1)
#define OFF_K   (5*M1)
#define OFF_VM  (6*M1)
#define OFF_VRM (7*M1)
#define OFF_PCOL (8*M1)                     // 4 segments x 32 bi x 1024 t
#define OFF_RMAX (8*M1 + 131072)
#define OFF_RINV (8*M1 + 163840)

__device__ float g_scratch[8*M1 + 196608];

// packed fp32x2 helpers (sm_100+)
#define FMA2(acc, a, b) \
    asm("fma.rn.f32x2 %0, %1, %2, %0;" : "+l"(acc) : "l"(a), "l"(b))
#define DUP2(dst, v) \
    asm("mov.b64 %0, {%1, %1};" : "=l"(dst) : "f"(v))
#define UNPACK2(lo, hi, v) \
    asm("mov.b64 {%0, %1}, %2;" : "=f"(lo), "=f"(hi) : "l"(v))

// ---------------------------------------------------------------------------
// K1: per-head projections  dst[b,h,t,d] = sum_dp src[b,t,h*32+dp] * W[dp,d]
// ---------------------------------------------------------------------------
__global__ __launch_bounds__(256) void proj_kernel(
    const float* __restrict__ x, const float* __restrict__ rx,
    const float* __restrict__ Wq, const float* __restrict__ Wk,
    const float* __restrict__ Wv, float* __restrict__ scratch)
{
    int tid = threadIdx.x;
    int which = blockIdx.y;
    const float* src = (which == 0 || which == 2) ? x : rx;
    const float* W = (which == 0) ? Wq : ((which == 1) ? Wk : Wv);
    float* dst = scratch + (size_t)which * M1;

    __shared__ float Ws[1024];
    __shared__ float Xs[8][32];
    for (int i = tid; i < 1024; i += 256) Ws[i] = W[i];

    int r = blockIdx.x * 8 + (tid >> 5);   // r = (b*8+h)*1024 + t
    int d = tid & 31;
    int b = r >> 13;
    int h = (r >> 10) & 7;
    int t = r & 1023;
    Xs[tid >> 5][d] = src[((size_t)(b * LL + t)) * DIMM + h * 32 + d];
    __syncthreads();

    float acc = 0.f;
    #pragma unroll
    for (int dp = 0; dp < 32; dp++) acc += Xs[tid >> 5][dp] * Ws[dp * 32 + d];
    dst[(size_t)r * 32 + d] = acc;
}

// ---------------------------------------------------------------------------
// K2: SPARSE binary gather-sum:  O[bh][l][d] = sum_{t: G[bh][l][t] > 0} X[bh][t][d]
// G values are exactly 0.0 / 1.0, so skipping zeros is bit-exact.
// One warp per output row; ballot-driven gather; dual accumulators.
// blockIdx.z: set 0 = (adj, xq -> q), set 1 = (adjr, xk -> k).
// ---------------------------------------------------------------------------
__global__ __launch_bounds__(256) void spmm_binary(
    const float* __restrict__ G0, const float* __restrict__ X0, float* __restrict__ O0,
    const float* __restrict__ G1, const float* __restrict__ X1, float* __restrict__ O1)
{
    int lane = threadIdx.x & 31, w = threadIdx.x >> 5;
    int l = blockIdx.x * 8 + w;
    int bh = blockIdx.y;
    const float* G = (blockIdx.z ? G1 : G0) + (size_t)bh * (LL * LL) + (size_t)l * LL;
    const float* X = (blockIdx.z ? X1 : X0) + (size_t)bh * (LL * DD);
    float* O = (blockIdx.z ? O1 : O0) + (size_t)bh * (LL * DD);

    float acc0 = 0.f, acc1 = 0.f;
    for (int t0 = 0; t0 < LL; t0 += 128) {
        float4 g = *(const float4*)&G[t0 + lane * 4];
        #pragma unroll
        for (int c = 0; c < 4; c++) {
            float gv = (c == 0) ? g.x : (c == 1) ? g.y : (c == 2) ? g.z : g.w;
            unsigned m = __ballot_sync(0xffffffffu, gv > 0.f);
            while (m) {
                int j = __ffs(m) - 1; m &= m - 1;
                acc0 += X[(t0 + j * 4 + c) * DD + lane];
                if (m) {
                    j = __ffs(m) - 1; m &= m - 1;
                    acc1 += X[(t0 + j * 4 + c) * DD + lane];
                }
            }
        }
    }
    O[(size_t)l * DD + lane] = acc0 + acc1;
}

// ---------------------------------------------------------------------------
// K2b: SPARSE weighted gather:  VM[b,l,h*32+d] = sum_{t: A[bh][l][t] > 0} A*X
// A entries are exact zeros where masked -> skip is bit-exact.
// ---------------------------------------------------------------------------
__global__ __launch_bounds__(256) void spmm_weighted(
    const float* __restrict__ A, const float* __restrict__ X, float* __restrict__ O)
{
    int lane = threadIdx.x & 31, w = threadIdx.x >> 5;
    int l = blockIdx.x * 8 + w;
    int bh = blockIdx.y;
    int b = bh >> 3, h = bh & 7;
    const float* G = A + (size_t)bh * (LL * LL) + (size_t)l * LL;
    const float* Xb = X + (size_t)bh * (LL * DD);

    float acc0 = 0.f, acc1 = 0.f;
    for (int t0 = 0; t0 < LL; t0 += 128) {
        float4 g = *(const float4*)&G[t0 + lane * 4];
        #pragma unroll
        for (int c = 0; c < 4; c++) {
            float gv = (c == 0) ? g.x : (c == 1) ? g.y : (c == 2) ? g.z : g.w;
            unsigned m = __ballot_sync(0xffffffffu, gv > 0.f);
            while (m) {
                int j = __ffs(m) - 1; m &= m - 1;
                float av = __shfl_sync(0xffffffffu, gv, j);
                acc0 += av * Xb[(t0 + j * 4 + c) * DD + lane];
                if (m) {
                    j = __ffs(m) - 1; m &= m - 1;
                    float av2 = __shfl_sync(0xffffffffu, gv, j);
                    acc1 += av2 * Xb[(t0 + j * 4 + c) * DD + lane];
                }
            }
        }
    }
    O[(size_t)b * (LL * DIMM) + (size_t)l * DIMM + h * 32 + lane] = acc0 + acc1;
}

// ---------------------------------------------------------------------------
// K2c: DENSE per-(b,h) SGEMM (used only for vr = Ar @ rv; Ar is dense).
// 128x32 tile, packed f32x2 FMA, register prefetch.
// ---------------------------------------------------------------------------
__global__ __launch_bounds__(256) void gemm_dense(
    const float* __restrict__ Amat, const float* __restrict__ Bm,
    float* __restrict__ C, size_t c_b_stride, size_t c_h_stride, int c_row_stride)
{
    __shared__ float Ast[32][132];   // transposed A tile [k][row]
    __shared__ float Bs[1024];       // [k][d]

    int tid = threadIdx.x;
    int bh = blockIdx.y;
    const float* A  = Amat + (size_t)bh * (LL * LL);
    const float* Bb = Bm + (size_t)bh * (LL * DD);
    float* Cb = C + (size_t)(bh >> 3) * c_b_stride + (size_t)(bh & 7) * c_h_stride;
    int l0 = blockIdx.x * 128;

    int d = tid & 31, rg = tid >> 5;
    int lrow = tid >> 1, cseg = (tid & 1) * 16;

    unsigned long long acc2[8];
    #pragma unroll
    for (int j = 0; j < 8; j++) acc2[j] = 0ULL;

    float4 pa0, pa1, pa2, pa3, pb;
    {
        const float* p = A + (size_t)(l0 + lrow) * LL + cseg;
        pa0 = *(const float4*)(p);      pa1 = *(const float4*)(p + 4);
        pa2 = *(const float4*)(p + 8);  pa3 = *(const float4*)(p + 12);
        pb  = *(const float4*)(Bb + tid * 4);
    }

    for (int c = 0; c < 32; c++) {
        Ast[cseg+ 0][lrow]=pa0.x; Ast[cseg+ 1][lrow]=pa0.y;
        Ast[cseg+ 2][lrow]=pa0.z; Ast[cseg+ 3][lrow]=pa0.w;
        Ast[cseg+ 4][lrow]=pa1.x; Ast[cseg+ 5][lrow]=pa1.y;
        Ast[cseg+ 6][lrow]=pa1.z; Ast[cseg+ 7][lrow]=pa1.w;
        Ast[cseg+ 8][lrow]=pa2.x; Ast[cseg+ 9][lrow]=pa2.y;
        Ast[cseg+10][lrow]=pa2.z; Ast[cseg+11][lrow]=pa2.w;
        Ast[cseg+12][lrow]=pa3.x; Ast[cseg+13][lrow]=pa3.y;
        Ast[cseg+14][lrow]=pa3.z; Ast[cseg+15][lrow]=pa3.w;
        *(float4*)&Bs[tid * 4] = pb;
        __syncthreads();

        if (c < 31) {
            int k0 = (c + 1) * 32;
            const float* p = A + (size_t)(l0 + lrow) * LL + k0 + cseg;
            pa0 = *(const float4*)(p);      pa1 = *(const float4*)(p + 4);
            pa2 = *(const float4*)(p + 8);  pa3 = *(const float4*)(p + 12);
            pb  = *(const float4*)(Bb + (size_t)k0 * DD + tid * 4);
        }

        #pragma unroll
        for (int kk = 0; kk < 32; kk++) {
            float bv = Bs[kk * 32 + d];
            unsigned long long bvv;
            DUP2(bvv, bv);
            const ulonglong2* ap = (const ulonglong2*)&Ast[kk][rg * 16];
            ulonglong2 q0 = ap[0];
            ulonglong2 q1 = ap[1];
            ulonglong2 q2 = ap[2];
            ulonglong2 q3 = ap[3];
            FMA2(acc2[0], q0.x, bvv); FMA2(acc2[1], q0.y, bvv);
            FMA2(acc2[2], q1.x, bvv); FMA2(acc2[3], q1.y, bvv);
            FMA2(acc2[4], q2.x, bvv); FMA2(acc2[5], q2.y, bvv);
            FMA2(acc2[6], q3.x, bvv); FMA2(acc2[7], q3.y, bvv);
        }
        __syncthreads();
    }

    #pragma unroll
    for (int j = 0; j < 8; j++) {
        float lo, hi;
        UNPACK2(lo, hi, acc2[j]);
        Cb[(size_t)(l0 + rg * 16 + 2*j    ) * c_row_stride + d] = lo;
        Cb[(size_t)(l0 + rg * 16 + 2*j + 1) * c_row_stride + d] = hi;
    }
}

// ---------------------------------------------------------------------------
// K3: logits + leaky + R head-mixing + mask -> raw logits (or -inf) in M_out;
// per-row max to rmax_out. Packed f32x2 phase A; double-buffered Ss; one
// __syncthreads per chunk (K staging is warp-private -> __syncwarp).
// ---------------------------------------------------------------------------
struct AttnSmem {
    float Qs[8][8][32];
    float Ss[2][8][8][32];
    float Ks[8][32][36];
    float Rs[64];
};

extern __shared__ unsigned char attn_smem_raw[];

__global__ __launch_bounds__(256) void attn_logits_kernel(
    const float* __restrict__ q, const float* __restrict__ k,
    const float* __restrict__ adj, const float* __restrict__ R,
    float* __restrict__ M_out, float* __restrict__ rmax_out)
{
    AttnSmem* S = (AttnSmem*)attn_smem_raw;
    int tid = threadIdx.x, w = tid >> 5, lane = tid & 31;
    int b = blockIdx.y, l0 = blockIdx.x * 8;

    for (int i = tid; i < 2048; i += 256) {
        int h = i >> 8, li = (i >> 5) & 7, d = i & 31;
        S->Qs[h][li][d] = q[((size_t)((b * 8 + h) * LL + l0 + li)) * 32 + d];
    }
    if (tid < 64) S->Rs[tid] = R[tid];

    float rmax[8];
    #pragma unroll
    for (int i = 0; i < 8; i++) rmax[i] = -INFINITY;
    __syncthreads();

    const int l = l0 + w;
    const float* kbase = k + (size_t)(b * 8 + w) * (LL * DD);  // head w

    for (int cch = 0; cch < 32; cch++) {
        int t0 = cch * 32;
        int buf = cch & 1;

        // stage K chunk: warp w loads head w's rows t0..t0+31 coalesced.
        // Ks[w] is written and read only by warp w -> __syncwarp suffices.
        #pragma unroll
        for (int j = 0; j < 8; j++) {
            int fi = j * 32 + lane;
            int t = fi >> 3, d4 = (fi & 7) * 4;
            *(float4*)&S->Ks[w][t][d4] =
                *(const float4*)(kbase + (size_t)(t0 + t) * DD + d4);
        }
        __syncwarp();

        // phase A: packed-f32x2 logits for head w; lane = k-row t0+lane
        {
            unsigned long long acc2[8];
            #pragma unroll
            for (int li = 0; li < 8; li++) acc2[li] = 0ULL;
            #pragma unroll
            for (int d8 = 0; d8 < 32; d8 += 8) {
                const ulonglong2* kp = (const ulonglong2*)&S->Ks[w][lane][d8];
                ulonglong2 k0 = kp[0], k1 = kp[1];
                #pragma unroll
                for (int li = 0; li < 8; li++) {
                    const ulonglong2* qp = (const ulonglong2*)&S->Qs[w][li][d8];
                    ulonglong2 q0 = qp[0], q1 = qp[1];
                    FMA2(acc2[li], q0.x, k0.x); FMA2(acc2[li], q0.y, k0.y);
                    FMA2(acc2[li], q1.x, k1.x); FMA2(acc2[li], q1.y, k1.y);
                }
            }
            #pragma unroll
            for (int li = 0; li < 8; li++) {
                float lo, hi;
                UNPACK2(lo, hi, acc2[li]);
                float s = (lo + hi) * ATT_SCALE;
                S->Ss[buf][w][li][lane] = (s > 0.f) ? s : 0.01f * s;  // leaky
            }
        }
        __syncthreads();

        // phase B: mixing + mask + running max for row li = w
        {
            float sv[8];
            #pragma unroll
            for (int h = 0; h < 8; h++) sv[h] = S->Ss[buf][h][w][lane];
            int t = t0 + lane;
            #pragma unroll
            for (int i = 0; i < 8; i++) {
                float m = 0.f;
                #pragma unroll
                for (int h = 0; h < 8; h++) m += S->Rs[i * 8 + h] * sv[h];
                size_t idx = ((size_t)((b * 8 + i) * LL + l)) * LL + t;
                float a = adj[idx];
                float o = (a > 0.f) ? m : -INFINITY;
                M_out[idx] = o;
                rmax[i] = fmaxf(rmax[i], o);
            }
        }
        // no trailing sync: next phase A writes the other Ss buffer; B(c) vs
        // A(c+2) on the same buffer is separated by the sync inside c+1.
    }

    #pragma unroll
    for (int i = 0; i < 8; i++) {
        float mx = rmax[i];
        #pragma unroll
        for (int off = 16; off; off >>= 1)
            mx = fmaxf(mx, __shfl_down_sync(0xffffffffu, mx, off));
        if (lane == 0) rmax_out[(b * 8 + i) * LL + l] = mx;
    }
}

// ---------------------------------------------------------------------------
// K3b: rinv[row] = 1 / sum_t exp(M[row,t] - rmax[row])
// ---------------------------------------------------------------------------
__global__ __launch_bounds__(256) void rowsum_kernel(
    const float* __restrict__ M, const float* __restrict__ rmax,
    float* __restrict__ rinv)
{
    int row = blockIdx.x * 8 + (threadIdx.x >> 5);
    int lane = threadIdx.x & 31;
    const float* r = M + (size_t)row * LL;
    float mx = rmax[row];
    float sum = 0.f;
    #pragma unroll
    for (int j = 0; j < 8; j++) {
        float4 v = *(const float4*)(r + (j * 32 + lane) * 4);
        sum += __expf(v.x - mx) + __expf(v.y - mx)
             + __expf(v.z - mx) + __expf(v.w - mx);
    }
    #pragma unroll
    for (int off = 16; off; off >>= 1)
        sum += __shfl_down_sync(0xffffffffu, sum, off);
    if (lane == 0) rinv[row] = 1.f / sum;
}

// ---------------------------------------------------------------------------
// K4: normalize A in place + partial transposed-softmax column sums.
// grid.z = row segment (256 rows each); partials to pcol[seg][bi][t].
// ---------------------------------------------------------------------------
__global__ __launch_bounds__(256) void norm_colsum_kernel(
    float* __restrict__ A, const float* __restrict__ rmax,
    const float* __restrict__ rinv, float* __restrict__ pcol)
{
    int bi = blockIdx.y;
    int seg = blockIdx.z;
    int t = blockIdx.x * 256 + threadIdx.x;
    float* base = A + (size_t)bi * (LL * LL);
    const float* mx = rmax + bi * LL;
    const float* iv = rinv + bi * LL;

    int lr0 = seg * 256;
    float s0 = 0.f, s1 = 0.f, s2 = 0.f, s3 = 0.f;
    for (int lr = lr0; lr < lr0 + 256; lr += 4) {
        float m0 = base[(size_t)(lr + 0) * LL + t];
        float m1 = base[(size_t)(lr + 1) * LL + t];
        float m2 = base[(size_t)(lr + 2) * LL + t];
        float m3 = base[(size_t)(lr + 3) * LL + t];
        float a0 = __expf(m0 - mx[lr + 0]) * iv[lr + 0];
        float a1 = __expf(m1 - mx[lr + 1]) * iv[lr + 1];
        float a2 = __expf(m2 - mx[lr + 2]) * iv[lr + 2];
        float a3 = __expf(m3 - mx[lr + 3]) * iv[lr + 3];
        base[(size_t)(lr + 0) * LL + t] = a0;
        base[(size_t)(lr + 1) * LL + t] = a1;
        base[(size_t)(lr + 2) * LL + t] = a2;
        base[(size_t)(lr + 3) * LL + t] = a3;
        s0 += __expf(a0); s1 += __expf(a1);
        s2 += __expf(a2); s3 += __expf(a3);
    }
    pcol[(size_t)(seg * 32 + bi) * LL + t] = (s0 + s1) + (s2 + s3);
}

// ---------------------------------------------------------------------------
// K5: Ar[b,i,t,l] = exp(A[b,i,l,t]) / colsum(t)   (tiled transpose; combines
// the 4 deterministic partial column sums).
// ---------------------------------------------------------------------------
__global__ __launch_bounds__(256) void transpose_exp_kernel(
    const float* __restrict__ A, const float* __restrict__ pcol,
    float* __restrict__ Ar)
{
    __shared__ float Ts[32][33];
    int bi = blockIdx.z;
    int l0 = blockIdx.x * 32, t0 = blockIdx.y * 32;
    int lane = threadIdx.x & 31, wr = threadIdx.x >> 5;
    const float* base = A + (size_t)bi * (LL * LL);
    float* obase = Ar + (size_t)bi * (LL * LL);
    #pragma unroll
    for (int j = 0; j < 4; j++) {
        int lr = wr + j * 8;
        Ts[lr][lane] = base[(size_t)(l0 + lr) * LL + t0 + lane];
    }
    __syncthreads();
    #pragma unroll
    for (int j = 0; j < 4; j++) {
        int tr = wr + j * 8;
        int tt = t0 + tr;
        float rc = 1.f / (pcol[(size_t)(0 * 32 + bi) * LL + tt]
                        + pcol[(size_t)(1 * 32 + bi) * LL + tt]
                        + pcol[(size_t)(2 * 32 + bi) * LL + tt]
                        + pcol[(size_t)(3 * 32 + bi) * LL + tt]);
        obase[(size_t)tt * LL + l0 + lane] = __expf(Ts[lane][tr]) * rc;
    }
}

// ---------------------------------------------------------------------------
// K6: Out[r,n] = sum_m gelu(Vm[r,m]) * Wp[m,n], packed f32x2 inner loop.
// ---------------------------------------------------------------------------
__device__ __forceinline__ float gelu_exact(float v)
{
    return 0.5f * v * (1.f + erff(v * 0.70710678118654752f));
}

__global__ __launch_bounds__(256) void out_gemm(
    const float* __restrict__ V0, const float* __restrict__ V1,
    const float* __restrict__ Wp,
    float* __restrict__ O0, float* __restrict__ O1)
{
    __shared__ float Gs[32][68];
    __shared__ float Ws[1024];
    const float* Vm = blockIdx.z ? V1 : V0;
    float* Out = blockIdx.z ? O1 : O0;
    int tid = threadIdx.x;
    int r0 = blockIdx.x * 64, n0 = blockIdx.y * 32;
    int d = tid & 31, rg = tid >> 5;
    int rrow = tid >> 2, cseg = (tid & 3) * 8;

    unsigned long long acc2[4];
    #pragma unroll
    for (int j = 0; j < 4; j++) acc2[j] = 0ULL;

    for (int k0 = 0; k0 < DIMM; k0 += 32) {
        const float* vrow = Vm + (size_t)(r0 + rrow) * DIMM + k0 + cseg;
        float4 a0 = *(const float4*)(vrow);
        float4 a1 = *(const float4*)(vrow + 4);
        Gs[cseg+0][rrow] = gelu_exact(a0.x); Gs[cseg+1][rrow] = gelu_exact(a0.y);
        Gs[cseg+2][rrow] = gelu_exact(a0.z); Gs[cseg+3][rrow] = gelu_exact(a0.w);
        Gs[cseg+4][rrow] = gelu_exact(a1.x); Gs[cseg+5][rrow] = gelu_exact(a1.y);
        Gs[cseg+6][rrow] = gelu_exact(a1.z); Gs[cseg+7][rrow] = gelu_exact(a1.w);
        *(float4*)&Ws[(tid >> 3) * 32 + (tid & 7) * 4] =
            *(const float4*)(Wp + (size_t)(k0 + (tid >> 3)) * DIMM + n0 + (tid & 7) * 4);
        __syncthreads();

        #pragma unroll
        for (int kk = 0; kk < 32; kk++) {
            float bv = Ws[kk * 32 + d];
            unsigned long long bvv;
            DUP2(bvv, bv);
            const ulonglong2* gp = (const ulonglong2*)&Gs[kk][rg * 8];
            ulonglong2 g0 = gp[0];
            ulonglong2 g1 = gp[1];
            FMA2(acc2[0], g0.x, bvv); FMA2(acc2[1], g0.y, bvv);
            FMA2(acc2[2], g1.x, bvv); FMA2(acc2[3], g1.y, bvv);
        }
        __syncthreads();
    }
    #pragma unroll
    for (int j = 0; j < 4; j++) {
        float lo, hi;
        UNPACK2(lo, hi, acc2[j]);
        Out[(size_t)(r0 + rg * 8 + 2*j    ) * DIMM + n0 + d] = lo;
        Out[(size_t)(r0 + rg * 8 + 2*j + 1) * DIMM + n0 + d] = hi;
    }
}

// ---------------------------------------------------------------------------
// Launch. Output layout (float32, reference return order):
//   out [4,1024,256] | out_resize [4,1024,256] | A [4,8,1024,1024] | Ar [...]
// ---------------------------------------------------------------------------
extern "C" void kernel_launch(void* const* d_in, const int* in_sizes, int n_in,
                              void* d_out, int out_size)
{
    const float* x    = (const float*)d_in[0];
    const float* rx   = (const float*)d_in[1];
    const float* adj  = (const float*)d_in[2];
    const float* adjr = (const float*)d_in[3];
    const float* Wq   = (const float*)d_in[4];
    const float* Wk   = (const float*)d_in[5];
    const float* Wv   = (const float*)d_in[6];
    const float* R    = (const float*)d_in[7];
    const float* Wp   = (const float*)d_in[8];

    float* out  = (float*)d_out;
    float* outr = out + (size_t)BB * LL * DIMM;
    float* A    = out + (size_t)2 * BB * LL * DIMM;
    float* Ar   = A + (size_t)BB * HH * LL * LL;

    float* s = nullptr;
    cudaGetSymbolAddress((void**)&s, g_scratch);

    cudaFuncSetAttribute(attn_logits_kernel,
                         cudaFuncAttributeMaxDynamicSharedMemorySize,
                         (int)sizeof(AttnSmem));

    // K1: projections (xq, xk, xv, rv)
    proj_kernel<<<dim3(4096, 4), 256>>>(x, rx, Wq, Wk, Wv, s);

    // K2: q = adj @ xq ; k = adjr @ xk  -- sparse binary gather (exact)
    spmm_binary<<<dim3(128, 32, 2), 256>>>(adj,  s + OFF_XQ, s + OFF_Q,
                                           adjr, s + OFF_XK, s + OFF_K);

    // K3: logits + mask -> raw m in A buffer; row max to scratch
    attn_logits_kernel<<<dim3(128, 4), 256, sizeof(AttnSmem)>>>(
        s + OFF_Q, s + OFF_K, adj, R, A, s + OFF_RMAX);

    // K3b: row sums -> rinv
    rowsum_kernel<<<4096, 256>>>(A, s + OFF_RMAX, s + OFF_RINV);

    // K4: normalize A in place + partial column sums (4 segments)
    norm_colsum_kernel<<<dim3(4, 32, 4), 256>>>(A, s + OFF_RMAX, s + OFF_RINV,
                                                s + OFF_PCOL);

    // K5: dual softmax on transpose -> Ar (combines partials)
    transpose_exp_kernel<<<dim3(32, 32, 32), 256>>>(A, s + OFF_PCOL, Ar);

    // v = A @ xv  -- sparse weighted gather (A zeros are exact)
    spmm_weighted<<<dim3(128, 32), 256>>>(A, s + OFF_XV, s + OFF_VM);

    // vr = Ar @ rv -- dense (Ar has no zeros)
    gemm_dense<<<dim3(8, 32), 256>>>(Ar, s + OFF_RV, s + OFF_VRM,
                                     (size_t)LL * DIMM, (size_t)DD, DIMM);

    // K6: out = gelu(v) @ Wp ; out_resize = gelu(vr) @ Wp
    out_gemm<<<dim3(64, 8, 2), 256>>>(s + OFF_VM, s + OFF_VRM, Wp, out, outr);
}